// round 15
// baseline (speedup 1.0000x reference)
#include <cuda_runtime.h>
#include <cstdint>

// ============================================================================
// GroupedExperts: out = (silu(x@gate) * (x@up)) @ down, per expert.
// 8 experts x 2048 tokens, DIM=2048, HIDDEN=5632, fp32.
// Plain sm_103 target => mma.sync m16n8k8 tf32 (no tcgen05/TMA).
// R15: fused gate+up kernel at 512 threads / 16 warps (warp tile 64x16,
// 64 acc regs) -> 4 warps/SMSP for latency hiding; down kernel = proven R8
// config (256 thr, occ 2). 3-stage cp.async ring, tf32 pre-round prologue.
// ============================================================================

#define NE    8
#define DIMX  2048
#define HID   5632
#define TPE   2048
#define NTOK  (NE * TPE)

// device scratch (no allocation allowed)
__device__ __align__(256) float g_xc[(size_t)NTOK * DIMX];     // tf32 x
__device__ __align__(256) float g_gc[(size_t)NE * DIMX * HID]; // tf32 gate
__device__ __align__(256) float g_uc[(size_t)NE * DIMX * HID]; // tf32 up
__device__ __align__(256) float g_dc[(size_t)NE * HID * DIMX]; // tf32 down
__device__ __align__(256) float g_h [(size_t)NTOK * HID];      // tf32 h

// ---- helpers ---------------------------------------------------------------
__device__ __forceinline__ uint32_t sptr(const void* p) {
    uint32_t a;
    asm("{ .reg .u64 t; cvta.to.shared.u64 t, %1; cvt.u32.u64 %0, t; }"
        : "=r"(a) : "l"(p));
    return a;
}
__device__ __forceinline__ void cp16(uint32_t s, const void* g) {
    asm volatile("cp.async.cg.shared.global [%0], [%1], 16;"
                 :: "r"(s), "l"(g) : "memory");
}
__device__ __forceinline__ float rna(float f) {
    uint32_t r;
    asm("cvt.rna.tf32.f32 %0, %1;" : "=r"(r) : "f"(f));
    return __uint_as_float(r);
}
__device__ __forceinline__ void mma8(float* d, const uint32_t* a,
                                     uint32_t b0, uint32_t b1) {
    asm volatile(
        "mma.sync.aligned.m16n8k8.row.col.f32.tf32.tf32.f32 "
        "{%0,%1,%2,%3}, {%4,%5,%6,%7}, {%8,%9}, {%0,%1,%2,%3};"
        : "+f"(d[0]), "+f"(d[1]), "+f"(d[2]), "+f"(d[3])
        : "r"(a[0]), "r"(a[1]), "r"(a[2]), "r"(a[3]), "r"(b0), "r"(b1));
}

// ---- prologue: tf32 round --------------------------------------------------
__global__ void cvt_tf32(const float4* __restrict__ in, float4* __restrict__ out,
                         size_t n4) {
    size_t i = (size_t)blockIdx.x * blockDim.x + threadIdx.x;
    const size_t stride = (size_t)gridDim.x * blockDim.x;
    for (; i < n4; i += stride) {
        float4 v = in[i];
        v.x = rna(v.x); v.y = rna(v.y); v.z = rna(v.z); v.w = rna(v.w);
        out[i] = v;
    }
}

// ---- shared constants ------------------------------------------------------
#define STAGES  3
#define APITCH  36
#define BPITCH  136
#define A_TILE_F (128 * APITCH)            // 4608 floats
#define B_TILE_F (32 * BPITCH)             // 4352 floats

// ===================== fused gate+up kernel =================================
// CTA 128M x 128N x 32K, 512 thr, 16 warps 2Mx8N, warp tile 64x16.
#define STAGE2_F (A_TILE_F + 2 * B_TILE_F) // 13312 floats
#define SMEM2    (STAGES * STAGE2_F * 4)   // 159744 B

__global__ void __launch_bounds__(512, 1) moe_fused(
    const float* __restrict__ A, const float* __restrict__ B0,
    const float* __restrict__ B1, float* __restrict__ C, int K, int Nw)
{
    extern __shared__ float sm[];
    const uint32_t smb = sptr(sm);
    const int tid = threadIdx.x, lid = tid & 31, wid = tid >> 5;
    const int wm = (wid & 1) << 6;              // 0 / 64
    const int wn = (wid >> 1) << 4;             // 0,16,...,112
    const int nb = blockIdx.x << 7;
    const int mb = blockIdx.y << 7;
    const int e  = mb / TPE;
    const float* Ab  = A  + (size_t)mb * K;
    const float* B0b = B0 + (size_t)e * K * Nw + nb;
    const float* B1b = B1 + (size_t)e * K * Nw + nb;
    const int NK = K >> 5;

    float accG[4][2][4], accU[4][2][4];
    #pragma unroll
    for (int mi = 0; mi < 4; mi++)
        #pragma unroll
        for (int ni = 0; ni < 2; ni++)
            #pragma unroll
            for (int q = 0; q < 4; q++) { accG[mi][ni][q] = 0.f; accU[mi][ni][q] = 0.f; }

    auto load = [&](int kc, int s) {
        const uint32_t sA  = smb + (uint32_t)(s * STAGE2_F) * 4;
        const uint32_t sB0 = sA + A_TILE_F * 4;
        const uint32_t sB1 = sB0 + B_TILE_F * 4;
        const float* gA  = Ab + kc * 32;
        const float* gB0 = B0b + (size_t)(kc * 32) * Nw;
        const float* gB1 = B1b + (size_t)(kc * 32) * Nw;
        #pragma unroll
        for (int i = 0; i < 2; i++) {           // A: 128 rows x 32 floats
            int idx = tid + (i << 9); int r = idx >> 3, j = idx & 7;
            cp16(sA + (uint32_t)(r * APITCH + (j << 2)) * 4,
                 gA + (size_t)r * K + (j << 2));
        }
        #pragma unroll
        for (int i = 0; i < 2; i++) {           // B: 32 rows x 128 floats
            int idx = tid + (i << 9); int r = idx >> 5, j = idx & 31;
            const uint32_t so = (uint32_t)(r * BPITCH + (j << 2)) * 4;
            const size_t go = (size_t)r * Nw + (j << 2);
            cp16(sB0 + so, gB0 + go);
            cp16(sB1 + so, gB1 + go);
        }
    };

    load(0, 0); asm volatile("cp.async.commit_group;" ::: "memory");
    load(1, 1); asm volatile("cp.async.commit_group;" ::: "memory");
    load(2, 2); asm volatile("cp.async.commit_group;" ::: "memory");

    int s = 0;
    const int l4 = lid >> 2, lm = lid & 3;
    #pragma unroll 1
    for (int kc = 0; kc < NK; kc++) {
        asm volatile("cp.async.wait_group 2;" ::: "memory");
        __syncthreads();

        const float* sA  = sm + s * STAGE2_F;
        const float* sB0 = sA + A_TILE_F;
        const float* sB1 = sB0 + B_TILE_F;

        #pragma unroll
        for (int ks = 0; ks < 4; ks++) {
            const int k0 = ks << 3;
            uint32_t af[4][4];
            #pragma unroll
            for (int mi = 0; mi < 4; mi++) {
                const int rb = wm + (mi << 4) + l4;
                const int c  = k0 + lm;
                af[mi][0] = __float_as_uint(sA[rb * APITCH + c]);
                af[mi][1] = __float_as_uint(sA[(rb + 8) * APITCH + c]);
                af[mi][2] = __float_as_uint(sA[rb * APITCH + c + 4]);
                af[mi][3] = __float_as_uint(sA[(rb + 8) * APITCH + c + 4]);
            }
            #pragma unroll
            for (int ni = 0; ni < 2; ni++) {
                const int cb = wn + (ni << 3) + l4;
                const int kr = k0 + lm;
                uint32_t b0 = __float_as_uint(sB0[kr * BPITCH + cb]);
                uint32_t b1 = __float_as_uint(sB0[(kr + 4) * BPITCH + cb]);
                #pragma unroll
                for (int mi = 0; mi < 4; mi++) mma8(accG[mi][ni], af[mi], b0, b1);
                uint32_t u0 = __float_as_uint(sB1[kr * BPITCH + cb]);
                uint32_t u1 = __float_as_uint(sB1[(kr + 4) * BPITCH + cb]);
                #pragma unroll
                for (int mi = 0; mi < 4; mi++) mma8(accU[mi][ni], af[mi], u0, u1);
            }
        }
        __syncthreads();
        if (kc + STAGES < NK) load(kc + STAGES, s);
        asm volatile("cp.async.commit_group;" ::: "memory");  // fixed cadence
        s = (s + 1 == STAGES) ? 0 : s + 1;
    }

    // epilogue: h = rna( silu(g) * u )
    #pragma unroll
    for (int mi = 0; mi < 4; mi++) {
        #pragma unroll
        for (int h2 = 0; h2 < 2; h2++) {
            const int r = mb + wm + (mi << 4) + (h2 << 3) + l4;
            float* Cr = C + (size_t)r * Nw + nb + wn + (lm << 1);
            #pragma unroll
            for (int ni = 0; ni < 2; ni++) {
                float g0 = accG[mi][ni][h2 * 2 + 0];
                float g1 = accG[mi][ni][h2 * 2 + 1];
                float u0 = accU[mi][ni][h2 * 2 + 0];
                float u1 = accU[mi][ni][h2 * 2 + 1];
                float c0 = rna(u0 * (g0 / (1.f + __expf(-g0))));
                float c1 = rna(u1 * (g1 / (1.f + __expf(-g1))));
                *(float2*)(Cr + (ni << 3)) = make_float2(c0, c1);
            }
        }
    }
}

// ===================== down-proj kernel (proven R8 config) ==================
// CTA 128M x 128N x 32K, 256 thr, warps 4Mx2N, warp tile 32x64, occ 2.
#define STAGED_F (A_TILE_F + B_TILE_F)     // 8960 floats
#define SMEMD    (STAGES * STAGED_F * 4)   // 107520 B

__global__ void __launch_bounds__(256, 2) moe_down(
    const float* __restrict__ A, const float* __restrict__ B0,
    float* __restrict__ C, int K, int Nw)
{
    extern __shared__ float sm[];
    const uint32_t smb = sptr(sm);
    const int tid = threadIdx.x, lid = tid & 31, wid = tid >> 5;
    const int wm = (wid & 3) << 5;              // 0..96
    const int wn = (wid >> 2) << 6;             // 0 / 64
    const int nb = blockIdx.x << 7;
    const int mb = blockIdx.y << 7;
    const int e  = mb / TPE;
    const float* Ab  = A  + (size_t)mb * K;
    const float* B0b = B0 + (size_t)e * K * Nw + nb;
    const int NK = K >> 5;

    float acc[2][8][4];
    #pragma unroll
    for (int mi = 0; mi < 2; mi++)
        #pragma unroll
        for (int ni = 0; ni < 8; ni++)
            #pragma unroll
            for (int q = 0; q < 4; q++) acc[mi][ni][q] = 0.f;

    auto load = [&](int kc, int s) {
        const uint32_t sA = smb + (uint32_t)(s * STAGED_F) * 4;
        const uint32_t sB = sA + A_TILE_F * 4;
        const float* gA = Ab + kc * 32;
        const float* gB = B0b + (size_t)(kc * 32) * Nw;
        #pragma unroll
        for (int i = 0; i < 4; i++) {           // A: 128 rows x 32 floats
            int idx = tid + (i << 8); int r = idx >> 3, j = idx & 7;
            cp16(sA + (uint32_t)(r * APITCH + (j << 2)) * 4,
                 gA + (size_t)r * K + (j << 2));
        }
        #pragma unroll
        for (int i = 0; i < 4; i++) {           // B: 32 rows x 128 floats
            int idx = tid + (i << 8); int r = idx >> 5, j = idx & 31;
            cp16(sB + (uint32_t)(r * BPITCH + (j << 2)) * 4,
                 gB + (size_t)r * Nw + (j << 2));
        }
    };

    load(0, 0); asm volatile("cp.async.commit_group;" ::: "memory");
    load(1, 1); asm volatile("cp.async.commit_group;" ::: "memory");
    load(2, 2); asm volatile("cp.async.commit_group;" ::: "memory");

    int s = 0;
    const int l4 = lid >> 2, lm = lid & 3;
    #pragma unroll 1
    for (int kc = 0; kc < NK; kc++) {
        asm volatile("cp.async.wait_group 2;" ::: "memory");
        __syncthreads();

        const float* sA = sm + s * STAGED_F;
        const float* sB = sA + A_TILE_F;

        #pragma unroll
        for (int ks = 0; ks < 4; ks++) {
            const int k0 = ks << 3;
            uint32_t af[2][4];
            #pragma unroll
            for (int mi = 0; mi < 2; mi++) {
                const int rb = wm + (mi << 4) + l4;
                const int c  = k0 + lm;
                af[mi][0] = __float_as_uint(sA[rb * APITCH + c]);
                af[mi][1] = __float_as_uint(sA[(rb + 8) * APITCH + c]);
                af[mi][2] = __float_as_uint(sA[rb * APITCH + c + 4]);
                af[mi][3] = __float_as_uint(sA[(rb + 8) * APITCH + c + 4]);
            }
            #pragma unroll
            for (int ni = 0; ni < 8; ni++) {
                const int cb = wn + (ni << 3) + l4;
                const int kr = k0 + lm;
                uint32_t b0 = __float_as_uint(sB[kr * BPITCH + cb]);
                uint32_t b1 = __float_as_uint(sB[(kr + 4) * BPITCH + cb]);
                mma8(acc[0][ni], af[0], b0, b1);
                mma8(acc[1][ni], af[1], b0, b1);
            }
        }
        __syncthreads();
        if (kc + STAGES < NK) load(kc + STAGES, s);
        asm volatile("cp.async.commit_group;" ::: "memory");  // fixed cadence
        s = (s + 1 == STAGES) ? 0 : s + 1;
    }

    // epilogue
    #pragma unroll
    for (int mi = 0; mi < 2; mi++) {
        #pragma unroll
        for (int h2 = 0; h2 < 2; h2++) {
            const int r = mb + wm + (mi << 4) + (h2 << 3) + l4;
            float* Cr = C + (size_t)r * Nw + nb + wn + (lm << 1);
            #pragma unroll
            for (int ni = 0; ni < 8; ni++) {
                *(float2*)(Cr + (ni << 3)) =
                    make_float2(acc[mi][ni][h2 * 2 + 0], acc[mi][ni][h2 * 2 + 1]);
            }
        }
    }
}

// ---- launch ----------------------------------------------------------------
extern "C" void kernel_launch(void* const* d_in, const int* in_sizes, int n_in,
                              void* d_out, int out_size) {
    (void)in_sizes; (void)n_in; (void)out_size;
    const float* x    = (const float*)d_in[0];
    const float* gate = (const float*)d_in[1];
    const float* up   = (const float*)d_in[2];
    const float* down = (const float*)d_in[3];
    float* out = (float*)d_out;

    void *pxc, *pgc, *puc, *pdc, *ph;
    cudaGetSymbolAddress(&pxc, g_xc);
    cudaGetSymbolAddress(&pgc, g_gc);
    cudaGetSymbolAddress(&puc, g_uc);
    cudaGetSymbolAddress(&pdc, g_dc);
    cudaGetSymbolAddress(&ph,  g_h);

    cudaFuncSetAttribute(moe_fused, cudaFuncAttributeMaxDynamicSharedMemorySize, SMEM2);
    cudaFuncSetAttribute(moe_down,  cudaFuncAttributeMaxDynamicSharedMemorySize, SMEMD);

    // Prologue: tf32-round all operands (exact feed-through in GEMMs).
    const size_t nx4 = (size_t)NTOK * DIMX / 4;
    const size_t nw4 = (size_t)NE * DIMX * HID / 4;
    cvt_tf32<<<8192, 256>>>((const float4*)x,    (float4*)pxc, nx4);
    cvt_tf32<<<8192, 256>>>((const float4*)gate, (float4*)pgc, nw4);
    cvt_tf32<<<8192, 256>>>((const float4*)up,   (float4*)puc, nw4);
    cvt_tf32<<<8192, 256>>>((const float4*)down, (float4*)pdc, nw4);

    // h = silu(x@gate) * (x@up)
    moe_fused<<<dim3(HID / 128, NTOK / 128), 512, SMEM2>>>(
        (const float*)pxc, (const float*)pgc, (const float*)puc,
        (float*)ph, DIMX, HID);
    // out = h @ down
    moe_down<<<dim3(DIMX / 128, NTOK / 128), 256, SMEMD>>>(
        (const float*)ph, (const float*)pdc, out, HID, DIMX);
}

// round 16
// speedup vs baseline: 1.8401x; 1.8401x over previous
#include <cuda_runtime.h>
#include <cuda_fp16.h>
#include <cstdint>

// ============================================================================
// GroupedExperts: out = (silu(x@gate) * (x@up)) @ down, per expert.
// 8 experts x 2048 tokens, DIM=2048, HIDDEN=5632, fp32.
// Plain sm_103 target => legacy mma.sync only (no tcgen05/TMA).
// R16: switch tf32 m16n8k8 -> fp16 m16n8k16 (same 10-bit mantissa precision,
// 2x MACs per instruction => the instruction-throughput ceiling doubles).
// Weights pre-converted to fp16 k-pair-interleaved [K/2][N] half2 words so a
// B fragment reg is one 32-bit LDS. h produced directly in fp16.
// Skeleton = proven R8: 3-stage cp.async ring, 4Mx2N warps, fixed cadence.
// ============================================================================

#define NE    8
#define DIMX  2048
#define HID   5632
#define TPE   2048
#define NTOK  (NE * TPE)

// device scratch (no allocation allowed)
__device__ __align__(256) uint16_t g_xh[(size_t)NTOK * DIMX];            // fp16 x
__device__ __align__(256) uint32_t g_gp[(size_t)NE * (DIMX/2) * HID];    // gate pairs
__device__ __align__(256) uint32_t g_up[(size_t)NE * (DIMX/2) * HID];    // up pairs
__device__ __align__(256) uint32_t g_dp[(size_t)NE * (HID/2) * DIMX];    // down pairs
__device__ __align__(256) uint16_t g_h [(size_t)NTOK * HID];             // fp16 h

// ---- helpers ---------------------------------------------------------------
__device__ __forceinline__ uint32_t sptr(const void* p) {
    uint32_t a;
    asm("{ .reg .u64 t; cvta.to.shared.u64 t, %1; cvt.u32.u64 %0, t; }"
        : "=r"(a) : "l"(p));
    return a;
}
__device__ __forceinline__ void cp16(uint32_t s, const void* g) {
    asm volatile("cp.async.cg.shared.global [%0], [%1], 16;"
                 :: "r"(s), "l"(g) : "memory");
}
__device__ __forceinline__ void mma16(float* d, const uint32_t* a,
                                      uint32_t b0, uint32_t b1) {
    asm volatile(
        "mma.sync.aligned.m16n8k16.row.col.f32.f16.f16.f32 "
        "{%0,%1,%2,%3}, {%4,%5,%6,%7}, {%8,%9}, {%0,%1,%2,%3};"
        : "+f"(d[0]), "+f"(d[1]), "+f"(d[2]), "+f"(d[3])
        : "r"(a[0]), "r"(a[1]), "r"(a[2]), "r"(a[3]), "r"(b0), "r"(b1));
}

// ---- prologue: fp32 -> fp16 (linear, for x) --------------------------------
__global__ void cvt_f16(const float4* __restrict__ in, uint2* __restrict__ out,
                        size_t n4) {
    size_t i = (size_t)blockIdx.x * blockDim.x + threadIdx.x;
    const size_t stride = (size_t)gridDim.x * blockDim.x;
    for (; i < n4; i += stride) {
        float4 v = in[i];
        __half2 lo = __floats2half2_rn(v.x, v.y);
        __half2 hi = __floats2half2_rn(v.z, v.w);
        uint2 o;
        o.x = *reinterpret_cast<uint32_t*>(&lo);
        o.y = *reinterpret_cast<uint32_t*>(&hi);
        out[i] = o;
    }
}

// ---- prologue: fp32 [e][Kd][Nd] -> fp16 k-pair words [e][Kd/2][Nd] ---------
__global__ void cvt_pair(const float* __restrict__ in, uint32_t* __restrict__ out,
                         int Kd, int Nd) {
    const size_t ein  = (size_t)blockIdx.z * Kd * Nd;
    const size_t eout = (size_t)blockIdx.z * (Kd / 2) * Nd;
    const int n  = (blockIdx.x << 8) + threadIdx.x;
    const int k2 = blockIdx.y;
    float v0 = in[ein + (size_t)(2 * k2)     * Nd + n];
    float v1 = in[ein + (size_t)(2 * k2 + 1) * Nd + n];
    __half2 h = __floats2half2_rn(v0, v1);          // low half = even k
    out[eout + (size_t)k2 * Nd + n] = *reinterpret_cast<uint32_t*>(&h);
}

// ---- GEMM config -----------------------------------------------------------
// CTA 128M x 128N x 64K-chunk; 256 thr, warps 4Mx2N, warp tile 32x64.
// A smem: halves [128][64] pitch 72 halves (36 words, 144B) -> 18432 B.
// B smem: half2 words [32 kp][128] pitch 136 words (544B)   -> 17408 B.
#define STAGES  3
#define APITCH_W 36
#define BPITCH_W 136
#define A_BYTES (128 * 144)
#define B_BYTES (32 * 544)
#define STAGE2_B (A_BYTES + 2 * B_BYTES)   // 53248
#define SMEM2    (STAGES * STAGE2_B)       // 159744
#define STAGED_B (A_BYTES + B_BYTES)       // 35840
#define SMEMD    (STAGES * STAGED_B)       // 107520

// ===================== fused gate+up kernel =================================
__global__ void __launch_bounds__(256, 1) moe_fused(
    const uint16_t* __restrict__ A, const uint32_t* __restrict__ B0,
    const uint32_t* __restrict__ B1, uint16_t* __restrict__ H, int K, int Nw)
{
    extern __shared__ char smc[];
    const uint32_t smb = sptr(smc);
    const int tid = threadIdx.x, lid = tid & 31, wid = tid >> 5;
    const int wm = (wid & 3) << 5;              // 0..96
    const int wn = (wid >> 2) << 6;             // 0 / 64
    const int nb = blockIdx.x << 7;
    const int mb = blockIdx.y << 7;
    const int e  = mb / TPE;
    const uint16_t* Ab  = A  + (size_t)mb * K;
    const uint32_t* B0b = B0 + ((size_t)e * (K / 2)) * Nw + nb;
    const uint32_t* B1b = B1 + ((size_t)e * (K / 2)) * Nw + nb;
    const int NK = K >> 6;                      // 64-K chunks

    float accG[2][8][4], accU[2][8][4];
    #pragma unroll
    for (int mi = 0; mi < 2; mi++)
        #pragma unroll
        for (int ni = 0; ni < 8; ni++)
            #pragma unroll
            for (int q = 0; q < 4; q++) { accG[mi][ni][q] = 0.f; accU[mi][ni][q] = 0.f; }

    auto load = [&](int kc, int s) {
        const uint32_t sA  = smb + (uint32_t)(s * STAGE2_B);
        const uint32_t sB0 = sA + A_BYTES;
        const uint32_t sB1 = sB0 + B_BYTES;
        const uint16_t* gA  = Ab + (size_t)kc * 64;
        const uint32_t* gB0 = B0b + (size_t)(kc * 32) * Nw;
        const uint32_t* gB1 = B1b + (size_t)(kc * 32) * Nw;
        #pragma unroll
        for (int i = 0; i < 4; i++) {           // A: 128 rows x 64 halves
            int idx = tid + (i << 8); int r = idx >> 3, j = idx & 7;
            cp16(sA + (uint32_t)(r * 144 + (j << 4)), gA + (size_t)r * K + (j << 3));
        }
        #pragma unroll
        for (int i = 0; i < 4; i++) {           // B: 32 kp-rows x 128 words
            int idx = tid + (i << 8); int r = idx >> 5, j = idx & 31;
            const uint32_t so = (uint32_t)(r * 544 + (j << 4));
            const size_t go = (size_t)r * Nw + (j << 2);
            cp16(sB0 + so, gB0 + go);
            cp16(sB1 + so, gB1 + go);
        }
    };

    load(0, 0); asm volatile("cp.async.commit_group;" ::: "memory");
    load(1, 1); asm volatile("cp.async.commit_group;" ::: "memory");
    load(2, 2); asm volatile("cp.async.commit_group;" ::: "memory");

    int s = 0;
    const int l4 = lid >> 2, lm = lid & 3;
    #pragma unroll 1
    for (int kc = 0; kc < NK; kc++) {
        asm volatile("cp.async.wait_group 2;" ::: "memory");
        __syncthreads();

        const uint32_t* wA  = (const uint32_t*)(smc + s * STAGE2_B);
        const uint32_t* wB0 = (const uint32_t*)(smc + s * STAGE2_B + A_BYTES);
        const uint32_t* wB1 = (const uint32_t*)(smc + s * STAGE2_B + A_BYTES + B_BYTES);

        #pragma unroll
        for (int ks = 0; ks < 4; ks++) {        // 4 x k16
            const int kw = ks << 3;             // word offset of k16 block
            uint32_t af[2][4];
            #pragma unroll
            for (int mi = 0; mi < 2; mi++) {
                const int rb = wm + (mi << 4) + l4;
                af[mi][0] = wA[rb * APITCH_W + kw + lm];
                af[mi][1] = wA[(rb + 8) * APITCH_W + kw + lm];
                af[mi][2] = wA[rb * APITCH_W + kw + lm + 4];
                af[mi][3] = wA[(rb + 8) * APITCH_W + kw + lm + 4];
            }
            #pragma unroll
            for (int ni = 0; ni < 8; ni++) {
                const int cb = wn + (ni << 3) + l4;
                uint32_t b0 = wB0[(kw + lm) * BPITCH_W + cb];
                uint32_t b1 = wB0[(kw + lm + 4) * BPITCH_W + cb];
                mma16(accG[0][ni], af[0], b0, b1);
                mma16(accG[1][ni], af[1], b0, b1);
                uint32_t u0 = wB1[(kw + lm) * BPITCH_W + cb];
                uint32_t u1 = wB1[(kw + lm + 4) * BPITCH_W + cb];
                mma16(accU[0][ni], af[0], u0, u1);
                mma16(accU[1][ni], af[1], u0, u1);
            }
        }
        __syncthreads();
        if (kc + STAGES < NK) load(kc + STAGES, s);
        asm volatile("cp.async.commit_group;" ::: "memory");  // fixed cadence
        s = (s + 1 == STAGES) ? 0 : s + 1;
    }

    // epilogue: h = fp16( silu(g) * u )
    #pragma unroll
    for (int mi = 0; mi < 2; mi++) {
        #pragma unroll
        for (int h2 = 0; h2 < 2; h2++) {
            const int r = mb + wm + (mi << 4) + (h2 << 3) + l4;
            uint16_t* Hr = H + (size_t)r * Nw + nb + wn + (lm << 1);
            #pragma unroll
            for (int ni = 0; ni < 8; ni++) {
                float g0 = accG[mi][ni][h2 * 2 + 0];
                float g1 = accG[mi][ni][h2 * 2 + 1];
                float u0 = accU[mi][ni][h2 * 2 + 0];
                float u1 = accU[mi][ni][h2 * 2 + 1];
                float c0 = u0 * (g0 / (1.f + __expf(-g0)));
                float c1 = u1 * (g1 / (1.f + __expf(-g1)));
                __half2 hh = __floats2half2_rn(c0, c1);
                *reinterpret_cast<uint32_t*>(Hr + (ni << 3)) =
                    *reinterpret_cast<uint32_t*>(&hh);
            }
        }
    }
}

// ===================== down-proj kernel =====================================
__global__ void __launch_bounds__(256, 2) moe_down(
    const uint16_t* __restrict__ A, const uint32_t* __restrict__ B0,
    float* __restrict__ C, int K, int Nw)
{
    extern __shared__ char smc[];
    const uint32_t smb = sptr(smc);
    const int tid = threadIdx.x, lid = tid & 31, wid = tid >> 5;
    const int wm = (wid & 3) << 5;
    const int wn = (wid >> 2) << 6;
    const int nb = blockIdx.x << 7;
    const int mb = blockIdx.y << 7;
    const int e  = mb / TPE;
    const uint16_t* Ab  = A  + (size_t)mb * K;
    const uint32_t* B0b = B0 + ((size_t)e * (K / 2)) * Nw + nb;
    const int NK = K >> 6;

    float acc[2][8][4];
    #pragma unroll
    for (int mi = 0; mi < 2; mi++)
        #pragma unroll
        for (int ni = 0; ni < 8; ni++)
            #pragma unroll
            for (int q = 0; q < 4; q++) acc[mi][ni][q] = 0.f;

    auto load = [&](int kc, int s) {
        const uint32_t sA = smb + (uint32_t)(s * STAGED_B);
        const uint32_t sB = sA + A_BYTES;
        const uint16_t* gA = Ab + (size_t)kc * 64;
        const uint32_t* gB = B0b + (size_t)(kc * 32) * Nw;
        #pragma unroll
        for (int i = 0; i < 4; i++) {
            int idx = tid + (i << 8); int r = idx >> 3, j = idx & 7;
            cp16(sA + (uint32_t)(r * 144 + (j << 4)), gA + (size_t)r * K + (j << 3));
        }
        #pragma unroll
        for (int i = 0; i < 4; i++) {
            int idx = tid + (i << 8); int r = idx >> 5, j = idx & 31;
            cp16(sB + (uint32_t)(r * 544 + (j << 4)), gB + (size_t)r * Nw + (j << 2));
        }
    };

    load(0, 0); asm volatile("cp.async.commit_group;" ::: "memory");
    load(1, 1); asm volatile("cp.async.commit_group;" ::: "memory");
    load(2, 2); asm volatile("cp.async.commit_group;" ::: "memory");

    int s = 0;
    const int l4 = lid >> 2, lm = lid & 3;
    #pragma unroll 1
    for (int kc = 0; kc < NK; kc++) {
        asm volatile("cp.async.wait_group 2;" ::: "memory");
        __syncthreads();

        const uint32_t* wA = (const uint32_t*)(smc + s * STAGED_B);
        const uint32_t* wB = (const uint32_t*)(smc + s * STAGED_B + A_BYTES);

        #pragma unroll
        for (int ks = 0; ks < 4; ks++) {
            const int kw = ks << 3;
            uint32_t af[2][4];
            #pragma unroll
            for (int mi = 0; mi < 2; mi++) {
                const int rb = wm + (mi << 4) + l4;
                af[mi][0] = wA[rb * APITCH_W + kw + lm];
                af[mi][1] = wA[(rb + 8) * APITCH_W + kw + lm];
                af[mi][2] = wA[rb * APITCH_W + kw + lm + 4];
                af[mi][3] = wA[(rb + 8) * APITCH_W + kw + lm + 4];
            }
            #pragma unroll
            for (int ni = 0; ni < 8; ni++) {
                const int cb = wn + (ni << 3) + l4;
                uint32_t b0 = wB[(kw + lm) * BPITCH_W + cb];
                uint32_t b1 = wB[(kw + lm + 4) * BPITCH_W + cb];
                mma16(acc[0][ni], af[0], b0, b1);
                mma16(acc[1][ni], af[1], b0, b1);
            }
        }
        __syncthreads();
        if (kc + STAGES < NK) load(kc + STAGES, s);
        asm volatile("cp.async.commit_group;" ::: "memory");  // fixed cadence
        s = (s + 1 == STAGES) ? 0 : s + 1;
    }

    // epilogue (fp32 out)
    #pragma unroll
    for (int mi = 0; mi < 2; mi++) {
        #pragma unroll
        for (int h2 = 0; h2 < 2; h2++) {
            const int r = mb + wm + (mi << 4) + (h2 << 3) + l4;
            float* Cr = C + (size_t)r * Nw + nb + wn + (lm << 1);
            #pragma unroll
            for (int ni = 0; ni < 8; ni++) {
                *(float2*)(Cr + (ni << 3)) =
                    make_float2(acc[mi][ni][h2 * 2 + 0], acc[mi][ni][h2 * 2 + 1]);
            }
        }
    }
}

// ---- launch ----------------------------------------------------------------
extern "C" void kernel_launch(void* const* d_in, const int* in_sizes, int n_in,
                              void* d_out, int out_size) {
    (void)in_sizes; (void)n_in; (void)out_size;
    const float* x    = (const float*)d_in[0];
    const float* gate = (const float*)d_in[1];
    const float* up   = (const float*)d_in[2];
    const float* down = (const float*)d_in[3];
    float* out = (float*)d_out;

    void *pxh, *pgp, *pup, *pdp, *ph;
    cudaGetSymbolAddress(&pxh, g_xh);
    cudaGetSymbolAddress(&pgp, g_gp);
    cudaGetSymbolAddress(&pup, g_up);
    cudaGetSymbolAddress(&pdp, g_dp);
    cudaGetSymbolAddress(&ph,  g_h);

    cudaFuncSetAttribute(moe_fused, cudaFuncAttributeMaxDynamicSharedMemorySize, SMEM2);
    cudaFuncSetAttribute(moe_down,  cudaFuncAttributeMaxDynamicSharedMemorySize, SMEMD);

    // Prologue: fp16 conversions.
    cvt_f16<<<4096, 256>>>((const float4*)x, (uint2*)pxh, (size_t)NTOK * DIMX / 4);
    cvt_pair<<<dim3(HID / 256, DIMX / 2, NE), 256>>>(gate, (uint32_t*)pgp, DIMX, HID);
    cvt_pair<<<dim3(HID / 256, DIMX / 2, NE), 256>>>(up,   (uint32_t*)pup, DIMX, HID);
    cvt_pair<<<dim3(DIMX / 256, HID / 2, NE), 256>>>(down, (uint32_t*)pdp, HID, DIMX);

    // h = silu(x@gate) * (x@up)
    moe_fused<<<dim3(HID / 128, NTOK / 128), 256, SMEM2>>>(
        (const uint16_t*)pxh, (const uint32_t*)pgp, (const uint32_t*)pup,
        (uint16_t*)ph, DIMX, HID);
    // out = h @ down
    moe_down<<<dim3(DIMX / 128, NTOK / 128), 256, SMEMD>>>(
        (const uint16_t*)ph, (const uint32_t*)pdp, out, HID, DIMX);
}

// round 17
// speedup vs baseline: 1.8992x; 1.0322x over previous
#include <cuda_runtime.h>
#include <cuda_fp16.h>
#include <cstdint>

// ============================================================================
// GroupedExperts: out = (silu(x@gate) * (x@up)) @ down, per expert.
// 8 experts x 2048 tokens, DIM=2048, HIDDEN=5632, fp32.
// Plain sm_103 target => legacy mma.sync only (no tcgen05/TMA).
// R17 (on top of the R16 fp16 m16n8k16 win):
//   - vectorized fp16 pair-conversion prologue (float4/uint4)
//   - fused gate+up kernel at 512 thr / 16 warps (4 warps/SMSP latency hiding)
//   - fused grid rastered M-fastest for expert-local L2/DRAM reuse
// ============================================================================

#define NE    8
#define DIMX  2048
#define HID   5632
#define TPE   2048
#define NTOK  (NE * TPE)

// device scratch (no allocation allowed)
__device__ __align__(256) uint16_t g_xh[(size_t)NTOK * DIMX];            // fp16 x
__device__ __align__(256) uint32_t g_gp[(size_t)NE * (DIMX/2) * HID];    // gate pairs
__device__ __align__(256) uint32_t g_up[(size_t)NE * (DIMX/2) * HID];    // up pairs
__device__ __align__(256) uint32_t g_dp[(size_t)NE * (HID/2) * DIMX];    // down pairs
__device__ __align__(256) uint16_t g_h [(size_t)NTOK * HID];             // fp16 h

// ---- helpers ---------------------------------------------------------------
__device__ __forceinline__ uint32_t sptr(const void* p) {
    uint32_t a;
    asm("{ .reg .u64 t; cvta.to.shared.u64 t, %1; cvt.u32.u64 %0, t; }"
        : "=r"(a) : "l"(p));
    return a;
}
__device__ __forceinline__ void cp16(uint32_t s, const void* g) {
    asm volatile("cp.async.cg.shared.global [%0], [%1], 16;"
                 :: "r"(s), "l"(g) : "memory");
}
__device__ __forceinline__ void mma16(float* d, const uint32_t* a,
                                      uint32_t b0, uint32_t b1) {
    asm volatile(
        "mma.sync.aligned.m16n8k16.row.col.f32.f16.f16.f32 "
        "{%0,%1,%2,%3}, {%4,%5,%6,%7}, {%8,%9}, {%0,%1,%2,%3};"
        : "+f"(d[0]), "+f"(d[1]), "+f"(d[2]), "+f"(d[3])
        : "r"(a[0]), "r"(a[1]), "r"(a[2]), "r"(a[3]), "r"(b0), "r"(b1));
}
__device__ __forceinline__ uint32_t packh2(float a, float b) {
    __half2 h = __floats2half2_rn(a, b);
    return *reinterpret_cast<uint32_t*>(&h);
}

// ---- prologue: fp32 -> fp16 (linear, for x) --------------------------------
__global__ void cvt_f16(const float4* __restrict__ in, uint2* __restrict__ out,
                        size_t n4) {
    size_t i = (size_t)blockIdx.x * blockDim.x + threadIdx.x;
    const size_t stride = (size_t)gridDim.x * blockDim.x;
    for (; i < n4; i += stride) {
        float4 v = in[i];
        uint2 o;
        o.x = packh2(v.x, v.y);
        o.y = packh2(v.z, v.w);
        out[i] = o;
    }
}

// ---- prologue: fp32 [e][Kd][Nd] -> fp16 k-pair words [e][Kd/2][Nd] ---------
// Vectorized: each thread converts 4 consecutive n at one k-pair row.
__global__ void cvt_pair(const float4* __restrict__ in, uint4* __restrict__ out,
                         int Kd, int Nd) {
    const int Nd4 = Nd >> 2;
    const size_t ein  = (size_t)blockIdx.z * Kd * Nd4;        // in float4 units
    const size_t eout = (size_t)blockIdx.z * (Kd >> 1) * Nd4; // in uint4 units
    const int n4 = (blockIdx.x << 7) + threadIdx.x;
    const int k2 = blockIdx.y;
    float4 r0 = in[ein + (size_t)(2 * k2)     * Nd4 + n4];
    float4 r1 = in[ein + (size_t)(2 * k2 + 1) * Nd4 + n4];
    uint4 o;
    o.x = packh2(r0.x, r1.x);   // low half = even k
    o.y = packh2(r0.y, r1.y);
    o.z = packh2(r0.z, r1.z);
    o.w = packh2(r0.w, r1.w);
    out[eout + (size_t)k2 * Nd4 + n4] = o;
}

// ---- GEMM config -----------------------------------------------------------
// K-chunk 64. A smem: halves [128][64], row 144 B (36 words). B smem: half2
// words [32 kp][128], row 544 B (136 words). Both pitches conflict-free.
#define STAGES  3
#define APITCH_W 36
#define BPITCH_W 136
#define A_BYTES (128 * 144)
#define B_BYTES (32 * 544)
#define STAGE2_B (A_BYTES + 2 * B_BYTES)   // 53248
#define SMEM2    (STAGES * STAGE2_B)       // 159744
#define STAGED_B (A_BYTES + B_BYTES)       // 35840
#define SMEMD    (STAGES * STAGED_B)       // 107520

// ===================== fused gate+up kernel =================================
// CTA 128M x 128N x 64K, 512 thr, 16 warps 2Mx8N, warp tile 64x16.
// Grid: x = M-tile (fast) for expert-local weight reuse, y = N-tile.
__global__ void __launch_bounds__(512, 1) moe_fused(
    const uint16_t* __restrict__ A, const uint32_t* __restrict__ B0,
    const uint32_t* __restrict__ B1, uint16_t* __restrict__ H, int K, int Nw)
{
    extern __shared__ char smc[];
    const uint32_t smb = sptr(smc);
    const int tid = threadIdx.x, lid = tid & 31, wid = tid >> 5;
    const int wm = (wid & 1) << 6;              // 0 / 64
    const int wn = (wid >> 1) << 4;             // 0,16,...,112
    const int mb = blockIdx.x << 7;             // M fast
    const int nb = blockIdx.y << 7;
    const int e  = mb / TPE;
    const uint16_t* Ab  = A  + (size_t)mb * K;
    const uint32_t* B0b = B0 + ((size_t)e * (K / 2)) * Nw + nb;
    const uint32_t* B1b = B1 + ((size_t)e * (K / 2)) * Nw + nb;
    const int NK = K >> 6;

    float accG[4][2][4], accU[4][2][4];
    #pragma unroll
    for (int mi = 0; mi < 4; mi++)
        #pragma unroll
        for (int ni = 0; ni < 2; ni++)
            #pragma unroll
            for (int q = 0; q < 4; q++) { accG[mi][ni][q] = 0.f; accU[mi][ni][q] = 0.f; }

    auto load = [&](int kc, int s) {
        const uint32_t sA  = smb + (uint32_t)(s * STAGE2_B);
        const uint32_t sB0 = sA + A_BYTES;
        const uint32_t sB1 = sB0 + B_BYTES;
        const uint16_t* gA  = Ab + (size_t)kc * 64;
        const uint32_t* gB0 = B0b + (size_t)(kc * 32) * Nw;
        const uint32_t* gB1 = B1b + (size_t)(kc * 32) * Nw;
        #pragma unroll
        for (int i = 0; i < 2; i++) {           // A: 128 rows x 64 halves
            int idx = tid + (i << 9); int r = idx >> 3, j = idx & 7;
            cp16(sA + (uint32_t)(r * 144 + (j << 4)), gA + (size_t)r * K + (j << 3));
        }
        #pragma unroll
        for (int i = 0; i < 2; i++) {           // B: 32 kp-rows x 128 words
            int idx = tid + (i << 9); int r = idx >> 5, j = idx & 31;
            const uint32_t so = (uint32_t)(r * 544 + (j << 4));
            const size_t go = (size_t)r * Nw + (j << 2);
            cp16(sB0 + so, gB0 + go);
            cp16(sB1 + so, gB1 + go);
        }
    };

    load(0, 0); asm volatile("cp.async.commit_group;" ::: "memory");
    load(1, 1); asm volatile("cp.async.commit_group;" ::: "memory");
    load(2, 2); asm volatile("cp.async.commit_group;" ::: "memory");

    int s = 0;
    const int l4 = lid >> 2, lm = lid & 3;
    #pragma unroll 1
    for (int kc = 0; kc < NK; kc++) {
        asm volatile("cp.async.wait_group 2;" ::: "memory");
        __syncthreads();

        const uint32_t* wA  = (const uint32_t*)(smc + s * STAGE2_B);
        const uint32_t* wB0 = (const uint32_t*)(smc + s * STAGE2_B + A_BYTES);
        const uint32_t* wB1 = (const uint32_t*)(smc + s * STAGE2_B + A_BYTES + B_BYTES);

        #pragma unroll
        for (int ks = 0; ks < 4; ks++) {        // 4 x k16
            const int kw = ks << 3;
            uint32_t af[4][4];
            #pragma unroll
            for (int mi = 0; mi < 4; mi++) {
                const int rb = wm + (mi << 4) + l4;
                af[mi][0] = wA[rb * APITCH_W + kw + lm];
                af[mi][1] = wA[(rb + 8) * APITCH_W + kw + lm];
                af[mi][2] = wA[rb * APITCH_W + kw + lm + 4];
                af[mi][3] = wA[(rb + 8) * APITCH_W + kw + lm + 4];
            }
            #pragma unroll
            for (int ni = 0; ni < 2; ni++) {
                const int cb = wn + (ni << 3) + l4;
                uint32_t b0 = wB0[(kw + lm) * BPITCH_W + cb];
                uint32_t b1 = wB0[(kw + lm + 4) * BPITCH_W + cb];
                #pragma unroll
                for (int mi = 0; mi < 4; mi++) mma16(accG[mi][ni], af[mi], b0, b1);
                uint32_t u0 = wB1[(kw + lm) * BPITCH_W + cb];
                uint32_t u1 = wB1[(kw + lm + 4) * BPITCH_W + cb];
                #pragma unroll
                for (int mi = 0; mi < 4; mi++) mma16(accU[mi][ni], af[mi], u0, u1);
            }
        }
        __syncthreads();
        if (kc + STAGES < NK) load(kc + STAGES, s);
        asm volatile("cp.async.commit_group;" ::: "memory");  // fixed cadence
        s = (s + 1 == STAGES) ? 0 : s + 1;
    }

    // epilogue: h = fp16( silu(g) * u )
    #pragma unroll
    for (int mi = 0; mi < 4; mi++) {
        #pragma unroll
        for (int h2 = 0; h2 < 2; h2++) {
            const int r = mb + wm + (mi << 4) + (h2 << 3) + l4;
            uint16_t* Hr = H + (size_t)r * Nw + nb + wn + (lm << 1);
            #pragma unroll
            for (int ni = 0; ni < 2; ni++) {
                float g0 = accG[mi][ni][h2 * 2 + 0];
                float g1 = accG[mi][ni][h2 * 2 + 1];
                float u0 = accU[mi][ni][h2 * 2 + 0];
                float u1 = accU[mi][ni][h2 * 2 + 1];
                float c0 = u0 * (g0 / (1.f + __expf(-g0)));
                float c1 = u1 * (g1 / (1.f + __expf(-g1)));
                *reinterpret_cast<uint32_t*>(Hr + (ni << 3)) = packh2(c0, c1);
            }
        }
    }
}

// ===================== down-proj kernel (proven R16 config) =================
__global__ void __launch_bounds__(256, 2) moe_down(
    const uint16_t* __restrict__ A, const uint32_t* __restrict__ B0,
    float* __restrict__ C, int K, int Nw)
{
    extern __shared__ char smc[];
    const uint32_t smb = sptr(smc);
    const int tid = threadIdx.x, lid = tid & 31, wid = tid >> 5;
    const int wm = (wid & 3) << 5;
    const int wn = (wid >> 2) << 6;
    const int nb = blockIdx.x << 7;
    const int mb = blockIdx.y << 7;
    const int e  = mb / TPE;
    const uint16_t* Ab  = A  + (size_t)mb * K;
    const uint32_t* B0b = B0 + ((size_t)e * (K / 2)) * Nw + nb;
    const int NK = K >> 6;

    float acc[2][8][4];
    #pragma unroll
    for (int mi = 0; mi < 2; mi++)
        #pragma unroll
        for (int ni = 0; ni < 8; ni++)
            #pragma unroll
            for (int q = 0; q < 4; q++) acc[mi][ni][q] = 0.f;

    auto load = [&](int kc, int s) {
        const uint32_t sA = smb + (uint32_t)(s * STAGED_B);
        const uint32_t sB = sA + A_BYTES;
        const uint16_t* gA = Ab + (size_t)kc * 64;
        const uint32_t* gB = B0b + (size_t)(kc * 32) * Nw;
        #pragma unroll
        for (int i = 0; i < 4; i++) {
            int idx = tid + (i << 8); int r = idx >> 3, j = idx & 7;
            cp16(sA + (uint32_t)(r * 144 + (j << 4)), gA + (size_t)r * K + (j << 3));
        }
        #pragma unroll
        for (int i = 0; i < 4; i++) {
            int idx = tid + (i << 8); int r = idx >> 5, j = idx & 31;
            cp16(sB + (uint32_t)(r * 544 + (j << 4)), gB + (size_t)r * Nw + (j << 2));
        }
    };

    load(0, 0); asm volatile("cp.async.commit_group;" ::: "memory");
    load(1, 1); asm volatile("cp.async.commit_group;" ::: "memory");
    load(2, 2); asm volatile("cp.async.commit_group;" ::: "memory");

    int s = 0;
    const int l4 = lid >> 2, lm = lid & 3;
    #pragma unroll 1
    for (int kc = 0; kc < NK; kc++) {
        asm volatile("cp.async.wait_group 2;" ::: "memory");
        __syncthreads();

        const uint32_t* wA = (const uint32_t*)(smc + s * STAGED_B);
        const uint32_t* wB = (const uint32_t*)(smc + s * STAGED_B + A_BYTES);

        #pragma unroll
        for (int ks = 0; ks < 4; ks++) {
            const int kw = ks << 3;
            uint32_t af[2][4];
            #pragma unroll
            for (int mi = 0; mi < 2; mi++) {
                const int rb = wm + (mi << 4) + l4;
                af[mi][0] = wA[rb * APITCH_W + kw + lm];
                af[mi][1] = wA[(rb + 8) * APITCH_W + kw + lm];
                af[mi][2] = wA[rb * APITCH_W + kw + lm + 4];
                af[mi][3] = wA[(rb + 8) * APITCH_W + kw + lm + 4];
            }
            #pragma unroll
            for (int ni = 0; ni < 8; ni++) {
                const int cb = wn + (ni << 3) + l4;
                uint32_t b0 = wB[(kw + lm) * BPITCH_W + cb];
                uint32_t b1 = wB[(kw + lm + 4) * BPITCH_W + cb];
                mma16(acc[0][ni], af[0], b0, b1);
                mma16(acc[1][ni], af[1], b0, b1);
            }
        }
        __syncthreads();
        if (kc + STAGES < NK) load(kc + STAGES, s);
        asm volatile("cp.async.commit_group;" ::: "memory");  // fixed cadence
        s = (s + 1 == STAGES) ? 0 : s + 1;
    }

    // epilogue (fp32 out)
    #pragma unroll
    for (int mi = 0; mi < 2; mi++) {
        #pragma unroll
        for (int h2 = 0; h2 < 2; h2++) {
            const int r = mb + wm + (mi << 4) + (h2 << 3) + l4;
            float* Cr = C + (size_t)r * Nw + nb + wn + (lm << 1);
            #pragma unroll
            for (int ni = 0; ni < 8; ni++) {
                *(float2*)(Cr + (ni << 3)) =
                    make_float2(acc[mi][ni][h2 * 2 + 0], acc[mi][ni][h2 * 2 + 1]);
            }
        }
    }
}

// ---- launch ----------------------------------------------------------------
extern "C" void kernel_launch(void* const* d_in, const int* in_sizes, int n_in,
                              void* d_out, int out_size) {
    (void)in_sizes; (void)n_in; (void)out_size;
    const float* x    = (const float*)d_in[0];
    const float* gate = (const float*)d_in[1];
    const float* up   = (const float*)d_in[2];
    const float* down = (const float*)d_in[3];
    float* out = (float*)d_out;

    void *pxh, *pgp, *pup, *pdp, *ph;
    cudaGetSymbolAddress(&pxh, g_xh);
    cudaGetSymbolAddress(&pgp, g_gp);
    cudaGetSymbolAddress(&pup, g_up);
    cudaGetSymbolAddress(&pdp, g_dp);
    cudaGetSymbolAddress(&ph,  g_h);

    cudaFuncSetAttribute(moe_fused, cudaFuncAttributeMaxDynamicSharedMemorySize, SMEM2);
    cudaFuncSetAttribute(moe_down,  cudaFuncAttributeMaxDynamicSharedMemorySize, SMEMD);

    // Prologue: fp16 conversions (vectorized).
    cvt_f16<<<8192, 256>>>((const float4*)x, (uint2*)pxh, (size_t)NTOK * DIMX / 4);
    cvt_pair<<<dim3(HID / 512, DIMX / 2, NE), 128>>>(
        (const float4*)gate, (uint4*)pgp, DIMX, HID);
    cvt_pair<<<dim3(HID / 512, DIMX / 2, NE), 128>>>(
        (const float4*)up,   (uint4*)pup, DIMX, HID);
    cvt_pair<<<dim3(DIMX / 512, HID / 2, NE), 128>>>(
        (const float4*)down, (uint4*)pdp, HID, DIMX);

    // h = silu(x@gate) * (x@up)   — M-fast raster
    moe_fused<<<dim3(NTOK / 128, HID / 128), 512, SMEM2>>>(
        (const uint16_t*)pxh, (const uint32_t*)pgp, (const uint32_t*)pup,
        (uint16_t*)ph, DIMX, HID);
    // out = h @ down
    moe_down<<<dim3(DIMX / 128, NTOK / 128), 256, SMEMD>>>(
        (const uint16_t*)ph, (const uint32_t*)pdp, out, HID, DIMX);
}